// round 9
// baseline (speedup 1.0000x reference)
#include <cuda_runtime.h>
#include <cstdint>

#define NN 50000
#define NE 800000

// ---------------- packed f32x2 helpers ----------------
#define FMA2(acc, a, b) \
    asm("fma.rn.f32x2 %0, %1, %2, %0;" : "+l"(acc) : "l"(a), "l"(b))
#define UNPACK2(lo, hi, in) \
    asm("mov.b64 {%0, %1}, %2;" : "=f"(lo), "=f"(hi) : "l"(in))

// ================= scratch =================
__device__ __align__(16) float g_agg[NN * 96];
__device__ __align__(16) float g_h1 [NN * 96];
__device__ __align__(16) float g_h2 [NN * 64];
__device__ __align__(16) float g_h3 [NN * 96];
__device__ __align__(16) float g_h4 [NN * 96];
__device__ __align__(16) float g_h5 [NN * 16];
__device__ __align__(16) float g_sum[96];
__device__ __align__(16) float g_sq [96];
__device__ __align__(16) float g_sc [5][96];
__device__ __align__(16) float g_sh [5][96];
// CSR scratch
__device__ int   g_deg      [NN];
__device__ int   g_row_start[NN];
__device__ int   g_pos      [NN];
__device__ int   g_csr_src  [NE];
__device__ float g_csr_ea   [NE];

// ================= CSR build (proven) =================
__global__ void hist_kernel(const int* __restrict__ dst, int* __restrict__ deg)
{
    int i = blockIdx.x * blockDim.x + threadIdx.x;
    if (i < NE) atomicAdd(&deg[dst[i]], 1);
}

__global__ void scan_kernel(const int* __restrict__ deg,
                            int* __restrict__ row_start,
                            int* __restrict__ pos)
{
    constexpr int T = 1024;
    constexpr int CH = (NN + T - 1) / T;
    __shared__ int warp_sums[32];
    int t = threadIdx.x;
    int base = t * CH;

    int s = 0;
    for (int i = 0; i < CH; i++) {
        int idx = base + i;
        if (idx < NN) s += deg[idx];
    }
    int lane = t & 31, wid = t >> 5;
    int v = s;
#pragma unroll
    for (int o = 1; o < 32; o <<= 1) {
        int u = __shfl_up_sync(0xffffffff, v, o);
        if (lane >= o) v += u;
    }
    if (lane == 31) warp_sums[wid] = v;
    __syncthreads();
    if (wid == 0) {
        int w = warp_sums[lane];
#pragma unroll
        for (int o = 1; o < 32; o <<= 1) {
            int u = __shfl_up_sync(0xffffffff, w, o);
            if (lane >= o) w += u;
        }
        warp_sums[lane] = w;
    }
    __syncthreads();
    int excl = v - s + (wid > 0 ? warp_sums[wid - 1] : 0);

    int running = excl;
    for (int i = 0; i < CH; i++) {
        int idx = base + i;
        if (idx < NN) {
            row_start[idx] = running;
            pos[idx]       = running;
            running += deg[idx];
        }
    }
}

__global__ void scatter_kernel(const int* __restrict__ src,
                               const int* __restrict__ dst,
                               const float* __restrict__ ea,
                               int* __restrict__ pos,
                               int* __restrict__ csr_src,
                               float* __restrict__ csr_ea)
{
    int i = blockIdx.x * blockDim.x + threadIdx.x;
    if (i >= NE) return;
    int slot = atomicAdd(&pos[dst[i]], 1);
    csr_src[slot] = src[i];
    csr_ea [slot] = ea[i];
}

// ================= CSR gather aggregation (4-edge ILP batches) =================
__global__ void __launch_bounds__(256)
aggregate_kernel(const float* __restrict__ xin,
                 const float* __restrict__ sc,
                 const float* __restrict__ sh,
                 const float* __restrict__ lw,
                 const float* __restrict__ lb,
                 const int* __restrict__ row_start,
                 const int* __restrict__ deg,
                 const int* __restrict__ csr_src,
                 const float* __restrict__ csr_ea,
                 float* __restrict__ agg)
{
    int w    = threadIdx.x >> 5;
    int lane = threadIdx.x & 31;
    int node = blockIdx.x * 8 + w;
    if (node >= NN) return;

    float lw0 = lw[lane], lw1 = lw[lane + 32], lw2 = lw[lane + 64];
    float lb0 = lb[lane], lb1 = lb[lane + 32], lb2 = lb[lane + 64];
    float sc0 = 1.f, sc1 = 1.f, sc2 = 1.f;
    float sh0 = 0.f, sh1 = 0.f, sh2 = 0.f;
    if (sc != nullptr) {
        sc0 = sc[lane]; sc1 = sc[lane + 32]; sc2 = sc[lane + 64];
        sh0 = sh[lane]; sh1 = sh[lane + 32]; sh2 = sh[lane + 64];
    }

    int s0 = row_start[node];
    int d  = deg[node];

    float a0 = 0.f, a1 = 0.f, a2 = 0.f;
    int e = 0;
    for (; e + 4 <= d; e += 4) {
        int   si[4]; float av[4];
#pragma unroll
        for (int j = 0; j < 4; j++) {
            si[j] = __ldg(csr_src + s0 + e + j);
            av[j] = __ldg(csr_ea  + s0 + e + j);
        }
        float x0[4], x1[4], x2[4];
#pragma unroll
        for (int j = 0; j < 4; j++) {
            const float* xr = xin + (size_t)si[j] * 96;
            x0[j] = __ldg(xr + lane);
            x1[j] = __ldg(xr + lane + 32);
            x2[j] = __ldg(xr + lane + 64);
        }
#pragma unroll
        for (int j = 0; j < 4; j++) {
            a0 += fmaxf(fmaf(x0[j], sc0, sh0) + fmaf(av[j], lw0, lb0), 0.f);
            a1 += fmaxf(fmaf(x1[j], sc1, sh1) + fmaf(av[j], lw1, lb1), 0.f);
            a2 += fmaxf(fmaf(x2[j], sc2, sh2) + fmaf(av[j], lw2, lb2), 0.f);
        }
    }
    for (; e < d; e++) {
        int   s = __ldg(csr_src + s0 + e);
        float a = __ldg(csr_ea  + s0 + e);
        const float* xr = xin + (size_t)s * 96;
        a0 += fmaxf(fmaf(__ldg(xr + lane),      sc0, sh0) + fmaf(a, lw0, lb0), 0.f);
        a1 += fmaxf(fmaf(__ldg(xr + lane + 32), sc1, sh1) + fmaf(a, lw1, lb1), 0.f);
        a2 += fmaxf(fmaf(__ldg(xr + lane + 64), sc2, sh2) + fmaf(a, lw2, lb2), 0.f);
    }
    float* ar = agg + (size_t)node * 96;
    ar[lane]      = a0;
    ar[lane + 32] = a1;
    ar[lane + 64] = a2;
}

// ================= FFMA2 GEMM + bias + ReLU + BN stats =================
// Micro-tile: 4 rows x 8 cols per thread; acc = 16 u64 (rows packed in pairs).
// W stored PRE-DUPLICATED {w,w} in smem -> zero packing in the hot loop.
// input row = affine(A) (+ Aadd) for cols < K1, affine2(B2) for cols >= K1
template<int BN, int TX, int TY>
__global__ void gemm2_kernel(const float* __restrict__ A,
                             const float* __restrict__ scA,
                             const float* __restrict__ shA,
                             const float* __restrict__ Aadd,
                             const float* __restrict__ B2,
                             const float* __restrict__ scB,
                             const float* __restrict__ shB,
                             int K, int K1,
                             const float* __restrict__ W,
                             const float* __restrict__ bias,
                             float* __restrict__ H,
                             float* __restrict__ gsum,
                             float* __restrict__ gsumsq,
                             int M)
{
    constexpr int BK = 32;
    constexpr int BM = TY * 4;
    constexpr int THREADS = TX * TY;
    constexpr int S = BM + 4;

    __shared__ float  At[BK][S];       // transposed A tile
    __shared__ float2 Wt[BK][BN];      // duplicated weights {w,w}
    __shared__ float  s_sum[BN];
    __shared__ float  s_sq [BN];

    const int tid = threadIdx.x;
    const int tx  = tid % TX;
    const int ty  = tid / TX;
    const int m0  = blockIdx.x * BM;
    const int K2  = K - K1;

    for (int t = tid; t < BN; t += THREADS) { s_sum[t] = 0.f; s_sq[t] = 0.f; }

    unsigned long long acc[2][8];
#pragma unroll
    for (int p = 0; p < 2; p++)
#pragma unroll
        for (int c = 0; c < 8; c++) acc[p][c] = 0ull;

    for (int kb = 0; kb < K; kb += BK) {
        // A tile (transposed); BK/4 == 8 float4 chunks per row
        for (int t = tid; t < BM * 8; t += THREADS) {
            int m  = t >> 3;
            int k4 = (t & 7) * 4;
            int row = m0 + m;
            float4 v = make_float4(0.f, 0.f, 0.f, 0.f);
            if (row < M) {
                int gc = kb + k4;
                if (B2 != nullptr && gc >= K1) {
                    int c2 = gc - K1;
                    v = *reinterpret_cast<const float4*>(B2 + (size_t)row * K2 + c2);
                    if (scB != nullptr) {
                        float4 sc4 = *reinterpret_cast<const float4*>(scB + c2);
                        float4 sh4 = *reinterpret_cast<const float4*>(shB + c2);
                        v.x = fmaf(v.x, sc4.x, sh4.x);
                        v.y = fmaf(v.y, sc4.y, sh4.y);
                        v.z = fmaf(v.z, sc4.z, sh4.z);
                        v.w = fmaf(v.w, sc4.w, sh4.w);
                    }
                } else {
                    v = *reinterpret_cast<const float4*>(A + (size_t)row * K1 + gc);
                    if (scA != nullptr) {
                        float4 sc4 = *reinterpret_cast<const float4*>(scA + gc);
                        float4 sh4 = *reinterpret_cast<const float4*>(shA + gc);
                        v.x = fmaf(v.x, sc4.x, sh4.x);
                        v.y = fmaf(v.y, sc4.y, sh4.y);
                        v.z = fmaf(v.z, sc4.z, sh4.z);
                        v.w = fmaf(v.w, sc4.w, sh4.w);
                    }
                    if (Aadd != nullptr) {
                        float4 v2 = *reinterpret_cast<const float4*>(Aadd + (size_t)row * K1 + gc);
                        v.x += v2.x; v.y += v2.y; v.z += v2.z; v.w += v2.w;
                    }
                }
            }
            At[k4 + 0][m] = v.x;
            At[k4 + 1][m] = v.y;
            At[k4 + 2][m] = v.z;
            At[k4 + 3][m] = v.w;
        }
        // W tile: duplicate at store time
        for (int t = tid; t < BK * (BN / 4); t += THREADS) {
            int k  = t / (BN / 4);
            int c4 = (t % (BN / 4)) * 4;
            float4 v = *reinterpret_cast<const float4*>(W + (size_t)(kb + k) * BN + c4);
            Wt[k][c4 + 0] = make_float2(v.x, v.x);
            Wt[k][c4 + 1] = make_float2(v.y, v.y);
            Wt[k][c4 + 2] = make_float2(v.z, v.z);
            Wt[k][c4 + 3] = make_float2(v.w, v.w);
        }
        __syncthreads();

#pragma unroll 8
        for (int k = 0; k < BK; k++) {
            ulonglong2 ap = *reinterpret_cast<const ulonglong2*>(&At[k][ty * 4]);
            ulonglong2 w01 = *reinterpret_cast<const ulonglong2*>(&Wt[k][tx * 8 + 0]);
            ulonglong2 w23 = *reinterpret_cast<const ulonglong2*>(&Wt[k][tx * 8 + 2]);
            ulonglong2 w45 = *reinterpret_cast<const ulonglong2*>(&Wt[k][tx * 8 + 4]);
            ulonglong2 w67 = *reinterpret_cast<const ulonglong2*>(&Wt[k][tx * 8 + 6]);
            unsigned long long wd[8] = {w01.x, w01.y, w23.x, w23.y,
                                        w45.x, w45.y, w67.x, w67.y};
#pragma unroll
            for (int c = 0; c < 8; c++) {
                FMA2(acc[0][c], ap.x, wd[c]);
                FMA2(acc[1][c], ap.y, wd[c]);
            }
        }
        __syncthreads();
    }

    // ---- epilogue: bias + relu + store + BN stats ----
    const int c0 = tx * 8;
    float bs[8];
    *reinterpret_cast<float4*>(bs)     = *reinterpret_cast<const float4*>(bias + c0);
    *reinterpret_cast<float4*>(bs + 4) = *reinterpret_cast<const float4*>(bias + c0 + 4);
    float csum[8], csq[8];
#pragma unroll
    for (int c = 0; c < 8; c++) { csum[c] = 0.f; csq[c] = 0.f; }

#pragma unroll
    for (int p = 0; p < 2; p++) {
        float lo[8], hi[8];
#pragma unroll
        for (int c = 0; c < 8; c++) UNPACK2(lo[c], hi[c], acc[p][c]);
#pragma unroll
        for (int rr = 0; rr < 2; rr++) {
            int row = m0 + ty * 4 + 2 * p + rr;
            if (row < M) {
                float* rv = rr ? hi : lo;
                float o[8];
#pragma unroll
                for (int c = 0; c < 8; c++) {
                    o[c] = fmaxf(rv[c] + bs[c], 0.f);
                    csum[c] += o[c];
                    csq [c] += o[c] * o[c];
                }
                float4* hp = reinterpret_cast<float4*>(H + (size_t)row * BN + c0);
                hp[0] = make_float4(o[0], o[1], o[2], o[3]);
                hp[1] = make_float4(o[4], o[5], o[6], o[7]);
            }
        }
    }
#pragma unroll
    for (int c = 0; c < 8; c++) {
        atomicAdd(&s_sum[c0 + c], csum[c]);
        atomicAdd(&s_sq [c0 + c], csq[c]);
    }
    __syncthreads();
    for (int t = tid; t < BN; t += THREADS) {
        atomicAdd(gsum   + t, s_sum[t]);
        atomicAdd(gsumsq + t, s_sq[t]);
    }
}

// ================= scalar GEMM (for N=16 layer; proven R2) =================
template<int BN, int TX, int TY, int TM>
__global__ void gemm_kernel(const float* __restrict__ A,
                            const float* __restrict__ scA,
                            const float* __restrict__ shA,
                            int K1,
                            const float* __restrict__ W,
                            const float* __restrict__ bias,
                            float* __restrict__ H,
                            float* __restrict__ gsum,
                            float* __restrict__ gsumsq,
                            int M)
{
    constexpr int BK = 32;
    constexpr int BM = TY * TM;
    constexpr int THREADS = TX * TY;
    constexpr int S = BM + 4;

    __shared__ float At[BK][S];
    __shared__ float Wt[BK][BN];
    __shared__ float s_sum[BN];
    __shared__ float s_sq [BN];

    const int tid = threadIdx.x;
    const int tx  = tid % TX;
    const int ty  = tid / TX;
    const int m0  = blockIdx.x * BM;

    for (int t = tid; t < BN; t += THREADS) { s_sum[t] = 0.f; s_sq[t] = 0.f; }

    float acc[TM][4];
#pragma unroll
    for (int i = 0; i < TM; i++) { acc[i][0]=0.f; acc[i][1]=0.f; acc[i][2]=0.f; acc[i][3]=0.f; }

    for (int kb = 0; kb < K1; kb += BK) {
        for (int t = tid; t < BM * 8; t += THREADS) {
            int m  = t >> 3;
            int k4 = (t & 7) * 4;
            int row = m0 + m;
            float4 v = make_float4(0.f, 0.f, 0.f, 0.f);
            if (row < M) {
                int gc = kb + k4;
                v = *reinterpret_cast<const float4*>(A + (size_t)row * K1 + gc);
                if (scA != nullptr) {
                    float4 sc4 = *reinterpret_cast<const float4*>(scA + gc);
                    float4 sh4 = *reinterpret_cast<const float4*>(shA + gc);
                    v.x = fmaf(v.x, sc4.x, sh4.x);
                    v.y = fmaf(v.y, sc4.y, sh4.y);
                    v.z = fmaf(v.z, sc4.z, sh4.z);
                    v.w = fmaf(v.w, sc4.w, sh4.w);
                }
            }
            At[k4 + 0][m] = v.x;
            At[k4 + 1][m] = v.y;
            At[k4 + 2][m] = v.z;
            At[k4 + 3][m] = v.w;
        }
        for (int t = tid; t < BK * (BN / 4); t += THREADS) {
            int k  = t / (BN / 4);
            int c4 = (t % (BN / 4)) * 4;
            float4 v = *reinterpret_cast<const float4*>(W + (size_t)(kb + k) * BN + c4);
            *reinterpret_cast<float4*>(&Wt[k][c4]) = v;
        }
        __syncthreads();

#pragma unroll 8
        for (int k = 0; k < BK; k++) {
            float4 wv = *reinterpret_cast<const float4*>(&Wt[k][tx * 4]);
            float av[TM];
            float2 a2 = *reinterpret_cast<const float2*>(&At[k][ty * TM]);
            av[0] = a2.x; av[1] = a2.y;
#pragma unroll
            for (int i = 0; i < TM; i++) {
                acc[i][0] = fmaf(av[i], wv.x, acc[i][0]);
                acc[i][1] = fmaf(av[i], wv.y, acc[i][1]);
                acc[i][2] = fmaf(av[i], wv.z, acc[i][2]);
                acc[i][3] = fmaf(av[i], wv.w, acc[i][3]);
            }
        }
        __syncthreads();
    }

    float4 b4 = *reinterpret_cast<const float4*>(bias + tx * 4);
    float csum[4] = {0.f, 0.f, 0.f, 0.f};
    float csq [4] = {0.f, 0.f, 0.f, 0.f};
#pragma unroll
    for (int i = 0; i < TM; i++) {
        int row = m0 + ty * TM + i;
        if (row < M) {
            float4 o;
            o.x = fmaxf(acc[i][0] + b4.x, 0.f);
            o.y = fmaxf(acc[i][1] + b4.y, 0.f);
            o.z = fmaxf(acc[i][2] + b4.z, 0.f);
            o.w = fmaxf(acc[i][3] + b4.w, 0.f);
            *reinterpret_cast<float4*>(H + (size_t)row * BN + tx * 4) = o;
            csum[0] += o.x; csum[1] += o.y; csum[2] += o.z; csum[3] += o.w;
            csq [0] += o.x * o.x; csq[1] += o.y * o.y; csq[2] += o.z * o.z; csq[3] += o.w * o.w;
        }
    }
    atomicAdd(&s_sum[tx * 4 + 0], csum[0]);
    atomicAdd(&s_sum[tx * 4 + 1], csum[1]);
    atomicAdd(&s_sum[tx * 4 + 2], csum[2]);
    atomicAdd(&s_sum[tx * 4 + 3], csum[3]);
    atomicAdd(&s_sq [tx * 4 + 0], csq[0]);
    atomicAdd(&s_sq [tx * 4 + 1], csq[1]);
    atomicAdd(&s_sq [tx * 4 + 2], csq[2]);
    atomicAdd(&s_sq [tx * 4 + 3], csq[3]);
    __syncthreads();
    for (int t = tid; t < BN; t += THREADS) {
        atomicAdd(gsum   + t, s_sum[t]);
        atomicAdd(gsumsq + t, s_sq[t]);
    }
}

// ================= BN finalize =================
__global__ void finalize_kernel(const float* __restrict__ gsum,
                                const float* __restrict__ gsumsq,
                                const float* __restrict__ g,
                                const float* __restrict__ beta,
                                float* __restrict__ scale,
                                float* __restrict__ shift,
                                int BNc, int M)
{
    int t = threadIdx.x;
    if (t < BNc) {
        float invM = 1.0f / (float)M;
        float mu   = gsum[t] * invM;
        float var  = gsumsq[t] * invM - mu * mu;
        float inv  = rsqrtf(var + 1e-5f);
        float sc   = g[t] * inv;
        scale[t] = sc;
        shift[t] = fmaf(-mu, sc, beta[t]);
    }
}

// ================= final output normalize =================
__global__ void norm_kernel(const float* __restrict__ Hin,
                            const float* __restrict__ scale,
                            const float* __restrict__ shift,
                            float* __restrict__ out, int n4, int cols4)
{
    int i = blockIdx.x * blockDim.x + threadIdx.x;
    if (i >= n4) return;
    int c4 = (i % cols4) * 4;
    float4 v  = reinterpret_cast<const float4*>(Hin)[i];
    float4 sc = *reinterpret_cast<const float4*>(scale + c4);
    float4 sh = *reinterpret_cast<const float4*>(shift + c4);
    float4 r;
    r.x = fmaf(v.x, sc.x, sh.x);
    r.y = fmaf(v.y, sc.y, sh.y);
    r.z = fmaf(v.z, sc.z, sh.z);
    r.w = fmaf(v.w, sc.w, sh.w);
    reinterpret_cast<float4*>(out)[i] = r;
}

// ================= host =================
extern "C" void kernel_launch(void* const* d_in, const int* in_sizes, int n_in,
                              void* d_out, int out_size)
{
    const float* x   = (const float*)d_in[0];
    const float* ea  = (const float*)d_in[1];
    const int*   ei  = (const int*)  d_in[2];
    const float* lw  = (const float*)d_in[3];
    const float* lb  = (const float*)d_in[4];
    const float* w1  = (const float*)d_in[5];
    const float* b1  = (const float*)d_in[6];
    const float* g1  = (const float*)d_in[7];
    const float* be1 = (const float*)d_in[8];
    const float* w2  = (const float*)d_in[9];
    const float* b2  = (const float*)d_in[10];
    const float* g2  = (const float*)d_in[11];
    const float* be2 = (const float*)d_in[12];
    const float* w3  = (const float*)d_in[13];
    const float* b3  = (const float*)d_in[14];
    const float* g3  = (const float*)d_in[15];
    const float* be3 = (const float*)d_in[16];
    const float* w4  = (const float*)d_in[17];
    const float* b4  = (const float*)d_in[18];
    const float* g4  = (const float*)d_in[19];
    const float* be4 = (const float*)d_in[20];
    const float* w5  = (const float*)d_in[21];
    const float* b5  = (const float*)d_in[22];
    const float* g5  = (const float*)d_in[23];
    const float* be5 = (const float*)d_in[24];
    float* out = (float*)d_out;

    const int* srcp = ei;
    const int* dstp = ei + NE;

    float *agg, *h1, *h2, *h3, *h4, *h5, *sum, *sq, *scb, *shb;
    int *deg, *row_start, *pos, *csr_src;
    float *csr_ea;
    cudaGetSymbolAddress((void**)&agg,       g_agg);
    cudaGetSymbolAddress((void**)&h1,        g_h1);
    cudaGetSymbolAddress((void**)&h2,        g_h2);
    cudaGetSymbolAddress((void**)&h3,        g_h3);
    cudaGetSymbolAddress((void**)&h4,        g_h4);
    cudaGetSymbolAddress((void**)&h5,        g_h5);
    cudaGetSymbolAddress((void**)&sum,       g_sum);
    cudaGetSymbolAddress((void**)&sq,        g_sq);
    cudaGetSymbolAddress((void**)&scb,       g_sc);
    cudaGetSymbolAddress((void**)&shb,       g_sh);
    cudaGetSymbolAddress((void**)&deg,       g_deg);
    cudaGetSymbolAddress((void**)&row_start, g_row_start);
    cudaGetSymbolAddress((void**)&pos,       g_pos);
    cudaGetSymbolAddress((void**)&csr_src,   g_csr_src);
    cudaGetSymbolAddress((void**)&csr_ea,    g_csr_ea);

    float* sc1 = scb + 0 * 96; float* sh1 = shb + 0 * 96;
    float* sc2 = scb + 1 * 96; float* sh2 = shb + 1 * 96;
    float* sc3 = scb + 2 * 96; float* sh3 = shb + 2 * 96;
    float* sc4 = scb + 3 * 96; float* sh4 = shb + 3 * 96;
    float* sc5 = scb + 4 * 96; float* sh5 = shb + 4 * 96;

    const int M = NN;
    const int eblk = (NE + 255) / 256;
    const int ablocks = (NN + 7) / 8;

    // ---- CSR build (shared by both convs) ----
    cudaMemsetAsync(deg, 0, NN * sizeof(int), 0);
    hist_kernel<<<eblk, 256>>>(dstp, deg);
    scan_kernel<<<1, 1024>>>(deg, row_start, pos);
    scatter_kernel<<<eblk, 256>>>(srcp, dstp, ea, pos, csr_src, csr_ea);

    // ---- conv1 ----
    aggregate_kernel<<<ablocks, 256>>>(x, nullptr, nullptr, lw, lb,
                                       row_start, deg, csr_src, csr_ea, agg);
    cudaMemsetAsync(sum, 0, 96 * sizeof(float), 0);
    cudaMemsetAsync(sq,  0, 96 * sizeof(float), 0);
    gemm2_kernel<96, 12, 16><<<(M + 63) / 64, 192>>>(x, nullptr, nullptr, agg,
                                                     nullptr, nullptr, nullptr,
                                                     96, 96, w1, b1, h1, sum, sq, M);
    finalize_kernel<<<1, 96>>>(sum, sq, g1, be1, sc1, sh1, 96, M);

    // ---- conv2 ----
    aggregate_kernel<<<ablocks, 256>>>(h1, sc1, sh1, lw, lb,
                                       row_start, deg, csr_src, csr_ea, agg);
    cudaMemsetAsync(sum, 0, 96 * sizeof(float), 0);
    cudaMemsetAsync(sq,  0, 96 * sizeof(float), 0);
    gemm2_kernel<64, 8, 24><<<(M + 95) / 96, 192>>>(h1, sc1, sh1, agg,
                                                    nullptr, nullptr, nullptr,
                                                    96, 96, w2, b2, h2, sum, sq, M);
    finalize_kernel<<<1, 64>>>(sum, sq, g2, be2, sc2, sh2, 64, M);

    // ---- lin1: concat(affine(h1), affine(h2)) @ w3 ----
    cudaMemsetAsync(sum, 0, 96 * sizeof(float), 0);
    cudaMemsetAsync(sq,  0, 96 * sizeof(float), 0);
    gemm2_kernel<96, 12, 16><<<(M + 63) / 64, 192>>>(h1, sc1, sh1, nullptr,
                                                     h2, sc2, sh2,
                                                     160, 96, w3, b3, h3, sum, sq, M);
    finalize_kernel<<<1, 96>>>(sum, sq, g3, be3, sc3, sh3, 96, M);

    // ---- mlp1a ----
    cudaMemsetAsync(sum, 0, 96 * sizeof(float), 0);
    cudaMemsetAsync(sq,  0, 96 * sizeof(float), 0);
    gemm2_kernel<96, 12, 16><<<(M + 63) / 64, 192>>>(h3, sc3, sh3, nullptr,
                                                     nullptr, nullptr, nullptr,
                                                     96, 96, w4, b4, h4, sum, sq, M);
    finalize_kernel<<<1, 96>>>(sum, sq, g4, be4, sc4, sh4, 96, M);

    // ---- mlp1b -> output ----
    cudaMemsetAsync(sum, 0, 96 * sizeof(float), 0);
    cudaMemsetAsync(sq,  0, 96 * sizeof(float), 0);
    gemm_kernel<16, 4, 32, 2><<<(M + 63) / 64, 128>>>(h4, sc4, sh4, 96,
                                                      w5, b5, h5, sum, sq, M);
    finalize_kernel<<<1, 16>>>(sum, sq, g5, be5, sc5, sh5, 16, M);
    norm_kernel<<<(M * 4 + 255) / 256, 256>>>(h5, sc5, sh5, out, M * 4, 4);

    (void)in_sizes; (void)n_in; (void)out_size;
}

// round 10
// speedup vs baseline: 2.1024x; 2.1024x over previous
#include <cuda_runtime.h>
#include <cstdint>

#define NN 50000
#define NE 800000

// ================= scratch =================
__device__ __align__(16) float g_agg[NN * 96];
__device__ __align__(16) float g_h1 [NN * 96];
__device__ __align__(16) float g_h2 [NN * 64];
__device__ __align__(16) float g_h3 [NN * 96];
__device__ __align__(16) float g_h4 [NN * 96];
__device__ __align__(16) float g_h5 [NN * 16];
__device__ __align__(16) float g_stats[5][192];   // [layer][sum(96) | sq(96)]
__device__ __align__(16) float g_sc [5][96];
__device__ __align__(16) float g_sh [5][96];
// CSR scratch
__device__ int   g_deg      [NN];
__device__ int   g_row_start[NN];
__device__ int   g_pos      [NN];
__device__ int   g_csr_src  [NE];
__device__ float g_csr_ea   [NE];

// ================= CSR build (proven) =================
__global__ void hist_kernel(const int* __restrict__ dst, int* __restrict__ deg)
{
    int i = blockIdx.x * blockDim.x + threadIdx.x;
    if (i < NE) atomicAdd(&deg[dst[i]], 1);
}

__global__ void scan_kernel(const int* __restrict__ deg,
                            int* __restrict__ row_start,
                            int* __restrict__ pos)
{
    constexpr int T = 1024;
    constexpr int CH = (NN + T - 1) / T;
    __shared__ int warp_sums[32];
    int t = threadIdx.x;
    int base = t * CH;

    int s = 0;
    for (int i = 0; i < CH; i++) {
        int idx = base + i;
        if (idx < NN) s += deg[idx];
    }
    int lane = t & 31, wid = t >> 5;
    int v = s;
#pragma unroll
    for (int o = 1; o < 32; o <<= 1) {
        int u = __shfl_up_sync(0xffffffff, v, o);
        if (lane >= o) v += u;
    }
    if (lane == 31) warp_sums[wid] = v;
    __syncthreads();
    if (wid == 0) {
        int w = warp_sums[lane];
#pragma unroll
        for (int o = 1; o < 32; o <<= 1) {
            int u = __shfl_up_sync(0xffffffff, w, o);
            if (lane >= o) w += u;
        }
        warp_sums[lane] = w;
    }
    __syncthreads();
    int excl = v - s + (wid > 0 ? warp_sums[wid - 1] : 0);

    int running = excl;
    for (int i = 0; i < CH; i++) {
        int idx = base + i;
        if (idx < NN) {
            row_start[idx] = running;
            pos[idx]       = running;
            running += deg[idx];
        }
    }
}

__global__ void scatter_kernel(const int* __restrict__ src,
                               const int* __restrict__ dst,
                               const float* __restrict__ ea,
                               int* __restrict__ pos,
                               int* __restrict__ csr_src,
                               float* __restrict__ csr_ea)
{
    int i = blockIdx.x * blockDim.x + threadIdx.x;
    if (i >= NE) return;
    int slot = atomicAdd(&pos[dst[i]], 1);
    csr_src[slot] = src[i];
    csr_ea [slot] = ea[i];
}

// ================= CSR gather aggregation (4-edge ILP batches, proven R9) =================
__global__ void __launch_bounds__(256)
aggregate_kernel(const float* __restrict__ xin,
                 const float* __restrict__ sc,
                 const float* __restrict__ sh,
                 const float* __restrict__ lw,
                 const float* __restrict__ lb,
                 const int* __restrict__ row_start,
                 const int* __restrict__ deg,
                 const int* __restrict__ csr_src,
                 const float* __restrict__ csr_ea,
                 float* __restrict__ agg)
{
    int w    = threadIdx.x >> 5;
    int lane = threadIdx.x & 31;
    int node = blockIdx.x * 8 + w;
    if (node >= NN) return;

    float lw0 = lw[lane], lw1 = lw[lane + 32], lw2 = lw[lane + 64];
    float lb0 = lb[lane], lb1 = lb[lane + 32], lb2 = lb[lane + 64];
    float sc0 = 1.f, sc1 = 1.f, sc2 = 1.f;
    float sh0 = 0.f, sh1 = 0.f, sh2 = 0.f;
    if (sc != nullptr) {
        sc0 = sc[lane]; sc1 = sc[lane + 32]; sc2 = sc[lane + 64];
        sh0 = sh[lane]; sh1 = sh[lane + 32]; sh2 = sh[lane + 64];
    }

    int s0 = row_start[node];
    int d  = deg[node];

    float a0 = 0.f, a1 = 0.f, a2 = 0.f;
    int e = 0;
    for (; e + 4 <= d; e += 4) {
        int   si[4]; float av[4];
#pragma unroll
        for (int j = 0; j < 4; j++) {
            si[j] = __ldg(csr_src + s0 + e + j);
            av[j] = __ldg(csr_ea  + s0 + e + j);
        }
        float x0[4], x1[4], x2[4];
#pragma unroll
        for (int j = 0; j < 4; j++) {
            const float* xr = xin + (size_t)si[j] * 96;
            x0[j] = __ldg(xr + lane);
            x1[j] = __ldg(xr + lane + 32);
            x2[j] = __ldg(xr + lane + 64);
        }
#pragma unroll
        for (int j = 0; j < 4; j++) {
            a0 += fmaxf(fmaf(x0[j], sc0, sh0) + fmaf(av[j], lw0, lb0), 0.f);
            a1 += fmaxf(fmaf(x1[j], sc1, sh1) + fmaf(av[j], lw1, lb1), 0.f);
            a2 += fmaxf(fmaf(x2[j], sc2, sh2) + fmaf(av[j], lw2, lb2), 0.f);
        }
    }
    for (; e < d; e++) {
        int   s = __ldg(csr_src + s0 + e);
        float a = __ldg(csr_ea  + s0 + e);
        const float* xr = xin + (size_t)s * 96;
        a0 += fmaxf(fmaf(__ldg(xr + lane),      sc0, sh0) + fmaf(a, lw0, lb0), 0.f);
        a1 += fmaxf(fmaf(__ldg(xr + lane + 32), sc1, sh1) + fmaf(a, lw1, lb1), 0.f);
        a2 += fmaxf(fmaf(__ldg(xr + lane + 64), sc2, sh2) + fmaf(a, lw2, lb2), 0.f);
    }
    float* ar = agg + (size_t)node * 96;
    ar[lane]      = a0;
    ar[lane + 32] = a1;
    ar[lane + 64] = a2;
}

// ================= scalar FFMA GEMM + bias + ReLU + BN stats (proven R2/R8) =================
// input row = affine(A) (+ Aadd) for cols < K1, affine2(B2) for cols >= K1
template<int BN, int TX, int TY, int TM>
__global__ void gemm_kernel(const float* __restrict__ A,
                            const float* __restrict__ scA,
                            const float* __restrict__ shA,
                            const float* __restrict__ Aadd,
                            const float* __restrict__ B2,
                            const float* __restrict__ scB,
                            const float* __restrict__ shB,
                            int K, int K1,
                            const float* __restrict__ W,
                            const float* __restrict__ bias,
                            float* __restrict__ H,
                            float* __restrict__ stats,   // [sum(96) | sq(96)] layout
                            int M)
{
    constexpr int BK = 32;
    constexpr int BM = TY * TM;
    constexpr int THREADS = TX * TY;
    constexpr int S = BM + 4;

    __shared__ float At[BK][S];
    __shared__ float Wt[BK][BN];
    __shared__ float s_sum[BN];
    __shared__ float s_sq [BN];

    const int tid = threadIdx.x;
    const int tx  = tid % TX;
    const int ty  = tid / TX;
    const int m0  = blockIdx.x * BM;
    const int K2  = K - K1;

    for (int t = tid; t < BN; t += THREADS) { s_sum[t] = 0.f; s_sq[t] = 0.f; }

    float acc[TM][4];
#pragma unroll
    for (int i = 0; i < TM; i++) { acc[i][0]=0.f; acc[i][1]=0.f; acc[i][2]=0.f; acc[i][3]=0.f; }

    for (int kb = 0; kb < K; kb += BK) {
        for (int t = tid; t < BM * (BK / 4); t += THREADS) {
            int m  = t >> 3;
            int k4 = (t & 7) * 4;
            int row = m0 + m;
            float4 v = make_float4(0.f, 0.f, 0.f, 0.f);
            if (row < M) {
                int gc = kb + k4;
                if (B2 != nullptr && gc >= K1) {
                    int c2 = gc - K1;
                    v = *reinterpret_cast<const float4*>(B2 + (size_t)row * K2 + c2);
                    if (scB != nullptr) {
                        float4 sc4 = *reinterpret_cast<const float4*>(scB + c2);
                        float4 sh4 = *reinterpret_cast<const float4*>(shB + c2);
                        v.x = fmaf(v.x, sc4.x, sh4.x);
                        v.y = fmaf(v.y, sc4.y, sh4.y);
                        v.z = fmaf(v.z, sc4.z, sh4.z);
                        v.w = fmaf(v.w, sc4.w, sh4.w);
                    }
                } else {
                    v = *reinterpret_cast<const float4*>(A + (size_t)row * K1 + gc);
                    if (scA != nullptr) {
                        float4 sc4 = *reinterpret_cast<const float4*>(scA + gc);
                        float4 sh4 = *reinterpret_cast<const float4*>(shA + gc);
                        v.x = fmaf(v.x, sc4.x, sh4.x);
                        v.y = fmaf(v.y, sc4.y, sh4.y);
                        v.z = fmaf(v.z, sc4.z, sh4.z);
                        v.w = fmaf(v.w, sc4.w, sh4.w);
                    }
                    if (Aadd != nullptr) {
                        float4 v2 = *reinterpret_cast<const float4*>(Aadd + (size_t)row * K1 + gc);
                        v.x += v2.x; v.y += v2.y; v.z += v2.z; v.w += v2.w;
                    }
                }
            }
            At[k4 + 0][m] = v.x;
            At[k4 + 1][m] = v.y;
            At[k4 + 2][m] = v.z;
            At[k4 + 3][m] = v.w;
        }
        for (int t = tid; t < BK * (BN / 4); t += THREADS) {
            int k  = t / (BN / 4);
            int c4 = (t % (BN / 4)) * 4;
            float4 v = *reinterpret_cast<const float4*>(W + (size_t)(kb + k) * BN + c4);
            *reinterpret_cast<float4*>(&Wt[k][c4]) = v;
        }
        __syncthreads();

#pragma unroll 8
        for (int k = 0; k < BK; k++) {
            float4 wv = *reinterpret_cast<const float4*>(&Wt[k][tx * 4]);
            float av[TM];
            if constexpr (TM % 4 == 0) {
#pragma unroll
                for (int ii = 0; ii < TM / 4; ii++) {
                    float4 a4 = *reinterpret_cast<const float4*>(&At[k][ty * TM + ii * 4]);
                    av[ii*4+0] = a4.x; av[ii*4+1] = a4.y; av[ii*4+2] = a4.z; av[ii*4+3] = a4.w;
                }
            } else {
                float2 a2 = *reinterpret_cast<const float2*>(&At[k][ty * TM]);
                av[0] = a2.x; av[1] = a2.y;
            }
#pragma unroll
            for (int i = 0; i < TM; i++) {
                acc[i][0] = fmaf(av[i], wv.x, acc[i][0]);
                acc[i][1] = fmaf(av[i], wv.y, acc[i][1]);
                acc[i][2] = fmaf(av[i], wv.z, acc[i][2]);
                acc[i][3] = fmaf(av[i], wv.w, acc[i][3]);
            }
        }
        __syncthreads();
    }

    float4 b4 = *reinterpret_cast<const float4*>(bias + tx * 4);
    float csum[4] = {0.f, 0.f, 0.f, 0.f};
    float csq [4] = {0.f, 0.f, 0.f, 0.f};
#pragma unroll
    for (int i = 0; i < TM; i++) {
        int row = m0 + ty * TM + i;
        if (row < M) {
            float4 o;
            o.x = fmaxf(acc[i][0] + b4.x, 0.f);
            o.y = fmaxf(acc[i][1] + b4.y, 0.f);
            o.z = fmaxf(acc[i][2] + b4.z, 0.f);
            o.w = fmaxf(acc[i][3] + b4.w, 0.f);
            *reinterpret_cast<float4*>(H + (size_t)row * BN + tx * 4) = o;
            csum[0] += o.x; csum[1] += o.y; csum[2] += o.z; csum[3] += o.w;
            csq [0] += o.x * o.x; csq[1] += o.y * o.y; csq[2] += o.z * o.z; csq[3] += o.w * o.w;
        }
    }
    atomicAdd(&s_sum[tx * 4 + 0], csum[0]);
    atomicAdd(&s_sum[tx * 4 + 1], csum[1]);
    atomicAdd(&s_sum[tx * 4 + 2], csum[2]);
    atomicAdd(&s_sum[tx * 4 + 3], csum[3]);
    atomicAdd(&s_sq [tx * 4 + 0], csq[0]);
    atomicAdd(&s_sq [tx * 4 + 1], csq[1]);
    atomicAdd(&s_sq [tx * 4 + 2], csq[2]);
    atomicAdd(&s_sq [tx * 4 + 3], csq[3]);
    __syncthreads();
    for (int t = tid; t < BN; t += THREADS) {
        atomicAdd(stats + t,      s_sum[t]);
        atomicAdd(stats + 96 + t, s_sq[t]);
    }
}

// ================= BN finalize =================
__global__ void finalize_kernel(const float* __restrict__ stats,
                                const float* __restrict__ g,
                                const float* __restrict__ beta,
                                float* __restrict__ scale,
                                float* __restrict__ shift,
                                int BNc, int M)
{
    int t = threadIdx.x;
    if (t < BNc) {
        float invM = 1.0f / (float)M;
        float mu   = stats[t] * invM;
        float var  = stats[96 + t] * invM - mu * mu;
        float inv  = rsqrtf(var + 1e-5f);
        float sc   = g[t] * inv;
        scale[t] = sc;
        shift[t] = fmaf(-mu, sc, beta[t]);
    }
}

// ================= final output normalize =================
__global__ void norm_kernel(const float* __restrict__ Hin,
                            const float* __restrict__ scale,
                            const float* __restrict__ shift,
                            float* __restrict__ out, int n4, int cols4)
{
    int i = blockIdx.x * blockDim.x + threadIdx.x;
    if (i >= n4) return;
    int c4 = (i % cols4) * 4;
    float4 v  = reinterpret_cast<const float4*>(Hin)[i];
    float4 sc = *reinterpret_cast<const float4*>(scale + c4);
    float4 sh = *reinterpret_cast<const float4*>(shift + c4);
    float4 r;
    r.x = fmaf(v.x, sc.x, sh.x);
    r.y = fmaf(v.y, sc.y, sh.y);
    r.z = fmaf(v.z, sc.z, sh.z);
    r.w = fmaf(v.w, sc.w, sh.w);
    reinterpret_cast<float4*>(out)[i] = r;
}

// ================= host =================
extern "C" void kernel_launch(void* const* d_in, const int* in_sizes, int n_in,
                              void* d_out, int out_size)
{
    const float* x   = (const float*)d_in[0];
    const float* ea  = (const float*)d_in[1];
    const int*   ei  = (const int*)  d_in[2];
    const float* lw  = (const float*)d_in[3];
    const float* lb  = (const float*)d_in[4];
    const float* w1  = (const float*)d_in[5];
    const float* b1  = (const float*)d_in[6];
    const float* g1  = (const float*)d_in[7];
    const float* be1 = (const float*)d_in[8];
    const float* w2  = (const float*)d_in[9];
    const float* b2  = (const float*)d_in[10];
    const float* g2  = (const float*)d_in[11];
    const float* be2 = (const float*)d_in[12];
    const float* w3  = (const float*)d_in[13];
    const float* b3  = (const float*)d_in[14];
    const float* g3  = (const float*)d_in[15];
    const float* be3 = (const float*)d_in[16];
    const float* w4  = (const float*)d_in[17];
    const float* b4  = (const float*)d_in[18];
    const float* g4  = (const float*)d_in[19];
    const float* be4 = (const float*)d_in[20];
    const float* w5  = (const float*)d_in[21];
    const float* b5  = (const float*)d_in[22];
    const float* g5  = (const float*)d_in[23];
    const float* be5 = (const float*)d_in[24];
    float* out = (float*)d_out;

    const int* srcp = ei;
    const int* dstp = ei + NE;

    float *agg, *h1, *h2, *h3, *h4, *h5, *stats, *scb, *shb;
    int *deg, *row_start, *pos, *csr_src;
    float *csr_ea;
    cudaGetSymbolAddress((void**)&agg,       g_agg);
    cudaGetSymbolAddress((void**)&h1,        g_h1);
    cudaGetSymbolAddress((void**)&h2,        g_h2);
    cudaGetSymbolAddress((void**)&h3,        g_h3);
    cudaGetSymbolAddress((void**)&h4,        g_h4);
    cudaGetSymbolAddress((void**)&h5,        g_h5);
    cudaGetSymbolAddress((void**)&stats,     g_stats);
    cudaGetSymbolAddress((void**)&scb,       g_sc);
    cudaGetSymbolAddress((void**)&shb,       g_sh);
    cudaGetSymbolAddress((void**)&deg,       g_deg);
    cudaGetSymbolAddress((void**)&row_start, g_row_start);
    cudaGetSymbolAddress((void**)&pos,       g_pos);
    cudaGetSymbolAddress((void**)&csr_src,   g_csr_src);
    cudaGetSymbolAddress((void**)&csr_ea,    g_csr_ea);

    float* st1 = stats + 0 * 192;
    float* st2 = stats + 1 * 192;
    float* st3 = stats + 2 * 192;
    float* st4 = stats + 3 * 192;
    float* st5 = stats + 4 * 192;
    float* sc1 = scb + 0 * 96; float* sh1 = shb + 0 * 96;
    float* sc2 = scb + 1 * 96; float* sh2 = shb + 1 * 96;
    float* sc3 = scb + 2 * 96; float* sh3 = shb + 2 * 96;
    float* sc4 = scb + 3 * 96; float* sh4 = shb + 3 * 96;
    float* sc5 = scb + 4 * 96; float* sh5 = shb + 4 * 96;

    const int M = NN;
    const int eblk = (NE + 255) / 256;
    const int ablocks = (NN + 7) / 8;

    // ---- one-shot zeroing of all BN stat buffers + CSR degree ----
    cudaMemsetAsync(stats, 0, 5 * 192 * sizeof(float), 0);
    cudaMemsetAsync(deg,   0, NN * sizeof(int), 0);

    // ---- CSR build (shared by both convs) ----
    hist_kernel<<<eblk, 256>>>(dstp, deg);
    scan_kernel<<<1, 1024>>>(deg, row_start, pos);
    scatter_kernel<<<eblk, 256>>>(srcp, dstp, ea, pos, csr_src, csr_ea);

    // ---- conv1 ----
    aggregate_kernel<<<ablocks, 256>>>(x, nullptr, nullptr, lw, lb,
                                       row_start, deg, csr_src, csr_ea, agg);
    gemm_kernel<96, 24, 8, 8><<<(M + 63) / 64, 192>>>(x, nullptr, nullptr, agg,
                                                      nullptr, nullptr, nullptr,
                                                      96, 96, w1, b1, h1, st1, M);
    finalize_kernel<<<1, 96>>>(st1, g1, be1, sc1, sh1, 96, M);

    // ---- conv2 ----
    aggregate_kernel<<<ablocks, 256>>>(h1, sc1, sh1, lw, lb,
                                       row_start, deg, csr_src, csr_ea, agg);
    gemm_kernel<64, 16, 16, 4><<<(M + 63) / 64, 256>>>(h1, sc1, sh1, agg,
                                                       nullptr, nullptr, nullptr,
                                                       96, 96, w2, b2, h2, st2, M);
    finalize_kernel<<<1, 64>>>(st2, g2, be2, sc2, sh2, 64, M);

    // ---- lin1: concat(affine(h1), affine(h2)) @ w3 ----
    gemm_kernel<96, 24, 8, 8><<<(M + 63) / 64, 192>>>(h1, sc1, sh1, nullptr,
                                                      h2, sc2, sh2,
                                                      160, 96, w3, b3, h3, st3, M);
    finalize_kernel<<<1, 96>>>(st3, g3, be3, sc3, sh3, 96, M);

    // ---- mlp1a ----
    gemm_kernel<96, 24, 8, 8><<<(M + 63) / 64, 192>>>(h3, sc3, sh3, nullptr,
                                                      nullptr, nullptr, nullptr,
                                                      96, 96, w4, b4, h4, st4, M);
    finalize_kernel<<<1, 96>>>(st4, g4, be4, sc4, sh4, 96, M);

    // ---- mlp1b -> output ----
    gemm_kernel<16, 4, 32, 2><<<(M + 63) / 64, 128>>>(h4, sc4, sh4, nullptr,
                                                      nullptr, nullptr, nullptr,
                                                      96, 96, w5, b5, h5, st5, M);
    finalize_kernel<<<1, 16>>>(st5, g5, be5, sc5, sh5, 16, M);
    norm_kernel<<<(M * 4 + 255) / 256, 256>>>(h5, sc5, sh5, out, M * 4, 4);

    (void)in_sizes; (void)n_in; (void)out_size;
}